// round 9
// baseline (speedup 1.0000x reference)
#include <cuda_runtime.h>

#define B_ 256
#define C_ 2048
#define N_ 288
#define K_ 6
#define NG_ 72            // float4 groups per row (288/4)
#define CHUNK_ 128        // c-columns per assign job
#define AJOBS_ (B_ * 16)  // (b, quarter, chunk) jobs = 4096

typedef unsigned long long u64;

// scratch (no allocations allowed)
__device__ unsigned char g_assign[B_ * N_];
__device__ float g_inv[B_ * K_];
// partial dots: [4096 jobs][7 (6 dots + xnorm)][288 n]  (~33 MB)
__device__ float g_part[(size_t)AJOBS_ * 7 * N_];

__device__ __forceinline__ u64 pack2(float lo, float hi) {
    u64 p;
    asm("mov.b64 %0, {%1, %2};" : "=l"(p) : "f"(lo), "f"(hi));
    return p;
}
__device__ __forceinline__ void unpack2(u64 p, float& lo, float& hi) {
    asm("mov.b64 {%0, %1}, %2;" : "=f"(lo), "=f"(hi) : "l"(p));
}
__device__ __forceinline__ void fma2(u64& d, u64 a, u64 b) {
    asm("fma.rn.f32x2 %0, %1, %2, %3;" : "=l"(d) : "l"(a), "l"(b), "l"(d));
}
__device__ __forceinline__ void add2(u64& d, u64 a) {
    asm("add.rn.f32x2 %0, %1, %2;" : "=l"(d) : "l"(d), "l"(a));
}

// ---------------------------------------------------------------------------
// Kernel A: partial dots, LDG.128 rolling pipeline.
// grid = 4096 jobs x 288 threads. Job = (b, quarter q, 128-c chunk).
// Thread: g = t/4 (one float4 of 4 n), r = t%4 (row in 4-row block).
// 32 steps; step s loads row c0+4s+r, cols [4g,4g+4) as float4, consumed
// 4 steps after issue. Clusters pre-duplicated as f32x2 in smem.
// ---------------------------------------------------------------------------
__global__ void __launch_bounds__(288, 3) assign_part_kernel(const float* __restrict__ x,
                                                             const float* __restrict__ cl) {
    __shared__ u64 sCl2[K_][CHUNK_];   // 6 KB duplicated cluster pairs

    const int job = blockIdx.x;
    const int b  = job >> 4;
    const int c0 = (job & 15) * CHUNK_;     // global column start
    const int t  = threadIdx.x;
    const int g  = t >> 2;                  // 0..71
    const int r  = t & 3;

    for (int i = t; i < K_ * CHUNK_; i += 288) {
        int k = i >> 7, cc = i & (CHUNK_ - 1);
        float v = cl[k * C_ + c0 + cc];
        sCl2[k][cc] = pack2(v, v);
    }
    __syncthreads();

    // float4 pointer: step s -> row (c0 + 4s + r), float4-col g.
    // row stride in float4 = 72; 4-row step stride = 288.
    const float4* xp = (const float4*)(x + (size_t)b * ((size_t)C_ * N_)
                                         + (size_t)(c0 + r) * N_) + g;

    u64 d2[K_][2];
    #pragma unroll
    for (int k = 0; k < K_; k++) { d2[k][0] = 0ull; d2[k][1] = 0ull; }
    u64 xn2[2] = {0ull, 0ull};

    float4 buf[4];
    #pragma unroll
    for (int j = 0; j < 4; j++) buf[j] = xp[(size_t)j * 288];

    #pragma unroll 1
    for (int s = 0; s < 32; s += 4) {
        #pragma unroll
        for (int j = 0; j < 4; j++) {
            float4 v = buf[j];
            if (s + j + 4 < 32) buf[j] = xp[(size_t)(s + j + 4) * 288];

            u64 v01 = pack2(v.x, v.y);
            u64 v23 = pack2(v.z, v.w);
            fma2(xn2[0], v01, v01);
            fma2(xn2[1], v23, v23);
            const int cc = 4 * (s + j) + r;
            #pragma unroll
            for (int k = 0; k < K_; k++) {
                u64 c2 = sCl2[k][cc];
                fma2(d2[k][0], v01, c2);
                fma2(d2[k][1], v23, c2);
            }
        }
    }

    // reduce partials across the 4 r-lanes (lanes 4q..4q+3 of each warp)
    #pragma unroll
    for (int k = 0; k < K_; k++) {
        #pragma unroll
        for (int h = 0; h < 2; h++) {
            add2(d2[k][h], __shfl_xor_sync(0xffffffffu, d2[k][h], 1));
            add2(d2[k][h], __shfl_xor_sync(0xffffffffu, d2[k][h], 2));
        }
    }
    #pragma unroll
    for (int h = 0; h < 2; h++) {
        add2(xn2[h], __shfl_xor_sync(0xffffffffu, xn2[h], 1));
        add2(xn2[h], __shfl_xor_sync(0xffffffffu, xn2[h], 2));
    }

    if (r == 0) {
        float* p = g_part + (size_t)job * 7 * N_ + 4 * g;
        #pragma unroll
        for (int k = 0; k < K_; k++) {
            *(u64*)(p + k * N_)     = d2[k][0];
            *(u64*)(p + k * N_ + 2) = d2[k][1];
        }
        *(u64*)(p + 6 * N_)     = xn2[0];
        *(u64*)(p + 6 * N_ + 2) = xn2[1];
    }
}

// ---------------------------------------------------------------------------
// Kernel C: combine 16 partials per batch, argmin, counts. grid = B.
// ---------------------------------------------------------------------------
__global__ void __launch_bounds__(N_) argmin_kernel(const float* __restrict__ cl) {
    __shared__ float sCn[K_];
    __shared__ int   sCnt[K_];

    const int b = blockIdx.x;
    const int t = threadIdx.x;
    const int w = t >> 5;
    const int l = t & 31;

    if (t < K_) sCnt[t] = 0;

    if (w < K_) {
        float s = 0.f;
        for (int c = l; c < C_; c += 32) {
            float v = __ldg(&cl[w * C_ + c]);
            s = fmaf(v, v, s);
        }
        #pragma unroll
        for (int o = 16; o; o >>= 1) s += __shfl_xor_sync(0xffffffffu, s, o);
        if (l == 0) sCn[w] = s;
    }
    __syncthreads();

    float dot[K_];
    #pragma unroll
    for (int k = 0; k < K_; k++) dot[k] = 0.f;
    float xn = 0.f;
    #pragma unroll 1
    for (int j = 0; j < 16; j++) {
        const float* p = g_part + ((size_t)(b * 16 + j) * 7) * N_ + t;
        #pragma unroll
        for (int k = 0; k < K_; k++) dot[k] += p[k * N_];
        xn += p[6 * N_];
    }

    int   a  = 0;
    float bd = (xn + sCn[0]) - 2.0f * dot[0];
    #pragma unroll
    for (int k = 1; k < K_; k++) {
        float e = (xn + sCn[k]) - 2.0f * dot[k];
        if (e < bd) { bd = e; a = k; }
    }
    g_assign[b * N_ + t] = (unsigned char)a;

    atomicAdd(&sCnt[a], 1);
    __syncthreads();
    if (t < K_) {
        int cnt = sCnt[t];
        g_inv[b * K_ + t] = (cnt > 0) ? (1.0f / (float)cnt) : 0.0f;
    }
}

// ---------------------------------------------------------------------------
// Kernel B: scatter-mean. grid = 16*B CTAs of 128 threads (4 warps).
// Warp <-> (b, 32 c-rows). Packed one-hot masks (27 FFMA2/row), 1-row
// register prefetch + 2-row-ahead L1 prefetch (lanes 0..8 cover the 9 lines,
// zero register cost), split-shuffle reduce.
// ---------------------------------------------------------------------------
__global__ void __launch_bounds__(128, 5) sum_kernel(const float* __restrict__ x,
                                                     float* __restrict__ out) {
    const int b = blockIdx.x & 255;
    const int q = blockIdx.x >> 8;
    const int w = threadIdx.x >> 5;
    const int l = threadIdx.x & 31;

    // packed one-hot masks for this lane's 9 positions (fixed per batch)
    u64 m2[9][3];
    #pragma unroll
    for (int j = 0; j < 9; j++) {
        int a = (int)g_assign[b * N_ + j * 32 + l];
        #pragma unroll
        for (int p = 0; p < 3; p++)
            m2[j][p] = pack2((a == 2 * p) ? 1.0f : 0.0f,
                             (a == 2 * p + 1) ? 1.0f : 0.0f);
    }

    const bool hi = (l >= 16);
    const int  lk = l & 15;
    const int  myk = lk + (hi ? 3 : 0);
    const float invSel = (lk < 3) ? g_inv[b * K_ + myk] : 0.0f;

    const float* xb = x + (size_t)b * ((size_t)C_ * N_);
    const int c0 = q * 128 + w * 32;

    float v[9], vn[9];
    {
        const float* row = xb + (size_t)c0 * N_;
        #pragma unroll
        for (int j = 0; j < 9; j++) v[j] = row[j * 32 + l];
        // prime the L1 for row c0+1 handled by vn below; prefetch row c0+2
        if (l < 9) {
            const float* pf = xb + (size_t)(c0 + 2) * N_ + l * 32;
            asm volatile("prefetch.global.L1 [%0];" :: "l"(pf));
        }
    }

    #pragma unroll 1
    for (int i = 0; i < 32; i++) {
        const int c = c0 + i;
        if (i + 1 < 32) {
            const float* rn = xb + (size_t)(c + 1) * N_;
            #pragma unroll
            for (int j = 0; j < 9; j++) vn[j] = rn[j * 32 + l];
        }
        // L1-prefetch row i+2 (one line per lane 0..8)
        if (i + 2 < 32 && l < 9) {
            const float* pf = xb + (size_t)(c + 2) * N_ + l * 32;
            asm volatile("prefetch.global.L1 [%0];" :: "l"(pf));
        }

        u64 s2[3];
        #pragma unroll
        for (int p = 0; p < 3; p++) s2[p] = 0ull;
        #pragma unroll
        for (int j = 0; j < 9; j++) {
            u64 vv = pack2(v[j], v[j]);
            #pragma unroll
            for (int p = 0; p < 3; p++) fma2(s2[p], m2[j][p], vv);
        }

        float s[K_];
        unpack2(s2[0], s[0], s[1]);
        unpack2(s2[1], s[2], s[3]);
        unpack2(s2[2], s[4], s[5]);

        float r0 = hi ? s[3] : s[0];
        float r1 = hi ? s[4] : s[1];
        float r2 = hi ? s[5] : s[2];
        float o0 = hi ? s[0] : s[3];
        float o1 = hi ? s[1] : s[4];
        float o2 = hi ? s[2] : s[5];
        r0 += __shfl_xor_sync(0xffffffffu, o0, 16);
        r1 += __shfl_xor_sync(0xffffffffu, o1, 16);
        r2 += __shfl_xor_sync(0xffffffffu, o2, 16);
        #pragma unroll
        for (int o = 8; o; o >>= 1) {
            r0 += __shfl_xor_sync(0xffffffffu, r0, o);
            r1 += __shfl_xor_sync(0xffffffffu, r1, o);
            r2 += __shfl_xor_sync(0xffffffffu, r2, o);
        }

        float res = r0;
        res = (lk == 1) ? r1 : res;
        res = (lk == 2) ? r2 : res;
        if (lk < 3) out[((size_t)b * C_ + c) * K_ + myk] = res * invSel;

        #pragma unroll
        for (int j = 0; j < 9; j++) v[j] = vn[j];
    }
}

extern "C" void kernel_launch(void* const* d_in, const int* in_sizes, int n_in,
                              void* d_out, int out_size) {
    const float* x  = (const float*)d_in[0];   // [256, 2048, 24, 12]
    const float* cl = (const float*)d_in[1];   // [6, 2048]
    float* out = (float*)d_out;                // [B, C, K]

    assign_part_kernel<<<AJOBS_, 288>>>(x, cl);
    argmin_kernel<<<B_, N_>>>(cl);
    sum_kernel<<<B_ * 16, 128>>>(x, out);
}